// round 15
// baseline (speedup 1.0000x reference)
#include <cuda_runtime.h>
#include <math.h>
#include <stdint.h>

// ---------------- problem dims ----------------
#define BATCH 16384
#define D_IN  1024
#define H_DIM 2048
#define O_DIM 2
#define DW (D_IN / 32)    // 32
#define HW (H_DIM / 32)   // 64

// Swizzles baked into the GLOBAL blocked layouts (match smem read patterns)
#define SWZA(row, k) ((((((k) >> 2) ^ (((row) >> 2) & 7)) << 2)) | ((k) & 3))
#define SWZW(col, k) ((((((k) >> 2) ^ ((col) & 7)) << 2)) | ((k) & 3))

// ---------------- device scratch (no allocs allowed) ----------------
__device__ __align__(16) unsigned g_actA[BATCH * HW];   // blocked [row][KW], SWZA image
__device__ __align__(16) unsigned g_actB[BATCH * HW];
__device__ __align__(16) unsigned g_w1 [H_DIM * DW];    // blocked [col][KW], SWZW image
__device__ __align__(16) unsigned g_w2 [H_DIM * HW];
__device__ __align__(16) unsigned g_w3 [H_DIM * HW];
__device__ __align__(16) unsigned g_woutb[O_DIM * HW];  // plain
__device__ float    g_thr [3 * H_DIM];

// ---------------- LOP3 helpers ----------------
__device__ __forceinline__ unsigned xor3(unsigned a, unsigned b, unsigned c) {
    unsigned r; asm("lop3.b32 %0, %1, %2, %3, 0x96;" : "=r"(r) : "r"(a), "r"(b), "r"(c)); return r;
}
__device__ __forceinline__ unsigned maj3(unsigned a, unsigned b, unsigned c) {
    unsigned r; asm("lop3.b32 %0, %1, %2, %3, 0xE8;" : "=r"(r) : "r"(a), "r"(b), "r"(c)); return r;
}
// forced IMAD accumulate (fma pipe): acc += p * w, w opaque runtime value
__device__ __forceinline__ void imad_acc(int& acc, unsigned p, int w) {
    asm("mad.lo.s32 %0, %1, %2, %0;" : "+r"(acc) : "r"(p), "r"(w));
}

// ---------------- fused thresholds (all 3 layers, one launch) ----------------
__global__ void compute_thr_all(const float* __restrict__ g1, const float* __restrict__ b1,
                                const float* __restrict__ m1, const float* __restrict__ v1,
                                const float* __restrict__ g2, const float* __restrict__ b2,
                                const float* __restrict__ m2, const float* __restrict__ v2,
                                const float* __restrict__ g3, const float* __restrict__ b3,
                                const float* __restrict__ m3, const float* __restrict__ v3,
                                float* __restrict__ thr)
{
    int i = blockIdx.x * blockDim.x + threadIdx.x;
    if (i >= 3 * H_DIM) return;
    int l = i >> 11, j = i & (H_DIM - 1);
    const float* g = (l == 0) ? g1 : (l == 1) ? g2 : g3;
    const float* b = (l == 0) ? b1 : (l == 1) ? b2 : b3;
    const float* m = (l == 0) ? m1 : (l == 1) ? m2 : m3;
    const float* v = (l == 0) ? v1 : (l == 1) ? v2 : v3;
    thr[i] = m[j] - b[j] * sqrtf(v[j] + 1e-5f) / g[j];
}

// pack src[rows][cwords*32] floats -> blocked-swizzled words. One warp = one row x 8 words,
// two independent load->ballot->shfl chains in flight (latency overlap).
// MODE 0 = activation swizzle (SWZA), MODE 1 = weight swizzle (SWZW)
template <int MODE>
__global__ void pack_bits_blk2(const float4* __restrict__ src, unsigned* __restrict__ dst,
                               int rows, int cwords, float cmp)
{
    int gid  = blockIdx.x * blockDim.x + threadIdx.x;
    int wrp  = gid >> 5;
    int lane = gid & 31;
    int wq   = cwords >> 3;              // 8-word groups per row
    if (wrp >= rows * wq) return;
    int row = wrp / wq, w0 = (wrp % wq) * 8;

    const float4* base = src + (size_t)row * (cwords * 8);
    float4 f0 = base[w0 * 8 + lane];
    float4 f1 = base[(w0 + 4) * 8 + lane];

    unsigned n0 = (f0.x < cmp ? 1u : 0u) | (f0.y < cmp ? 2u : 0u)
                | (f0.z < cmp ? 4u : 0u) | (f0.w < cmp ? 8u : 0u);
    unsigned n1 = (f1.x < cmp ? 1u : 0u) | (f1.y < cmp ? 2u : 0u)
                | (f1.z < cmp ? 4u : 0u) | (f1.w < cmp ? 8u : 0u);
    unsigned v0 = n0 << ((lane & 7) * 4);
    unsigned v1 = n1 << ((lane & 7) * 4);
    v0 |= __shfl_xor_sync(0xffffffffu, v0, 1);
    v1 |= __shfl_xor_sync(0xffffffffu, v1, 1);
    v0 |= __shfl_xor_sync(0xffffffffu, v0, 2);
    v1 |= __shfl_xor_sync(0xffffffffu, v1, 2);
    v0 |= __shfl_xor_sync(0xffffffffu, v0, 4);
    v1 |= __shfl_xor_sync(0xffffffffu, v1, 4);
    if ((lane & 7) == 0) {
        int wA = w0 + (lane >> 3);
        int wB = wA + 4;
        int sA = (MODE == 0) ? SWZA(row, wA) : SWZW(row, wA);
        int sB = (MODE == 0) ? SWZA(row, wB) : SWZW(row, wB);
        dst[(size_t)row * cwords + sA] = v0;
        dst[(size_t)row * cwords + sB] = v1;
    }
}

__global__ void pack_bits_plain(const float* __restrict__ src, unsigned* __restrict__ dst,
                                int nwords, float cmp)
{
    int gid = blockIdx.x * blockDim.x + threadIdx.x;
    int w = gid >> 5;
    if (w >= nwords) return;
    int lane = gid & 31;
    float v = src[(size_t)w * 32 + lane];
    unsigned msk = __ballot_sync(0xffffffffu, v < cmp);
    if (lane == 0) dst[w] = msk;
}

// ---------------- CSA-popc binary GEMM (R7/R9 structure; IMAD accumulate) ----------------
// CTA tile 64 rows x 64 cols, 256 threads = 8 warps (4 row-groups x 2 col-groups).
// Warp: 16 rows x 32 cols. Lane: 4 rows x 4 cols; 8-word K window, 4-CSA tree.
template <int KW>
__global__ __launch_bounds__(256, 2)
void bgemm_csa(const unsigned* __restrict__ Apk,   // blocked [row][KW] SWZA image
               const unsigned* __restrict__ Wpk,   // blocked [col][KW] SWZW image
               const float*    __restrict__ thr,
               unsigned*       __restrict__ OutN,  // blocked [row][HW] SWZA image
               int w1i, int w2i, int w4i)          // opaque 1, 2, 4
{
    __shared__ unsigned sA[64 * KW];
    __shared__ unsigned sW[64 * KW];

    const int tid  = threadIdx.x;
    const int lane = tid & 31;
    const int wid  = tid >> 5;
    const int warpM = wid & 3;
    const int warpN = wid >> 2;
    const int r0 = blockIdx.x * 64;
    const int c0 = blockIdx.y * 64;

    // linear vectorized fills: global image == smem image (swizzle pre-baked)
    {
        const uint4* asrc = (const uint4*)(Apk + (size_t)r0 * KW);
        uint4* ad = (uint4*)sA;
        #pragma unroll
        for (int i = tid; i < 16 * KW; i += 256) ad[i] = asrc[i];
        const uint4* wsrc = (const uint4*)(Wpk + (size_t)c0 * KW);
        uint4* wd = (uint4*)sW;
        #pragma unroll
        for (int i = tid; i < 16 * KW; i += 256) wd[i] = wsrc[i];
    }
    __syncthreads();

    int acc[4][4];
    #pragma unroll
    for (int r = 0; r < 4; ++r)
        #pragma unroll
        for (int j = 0; j < 4; ++j) acc[r][j] = 0;

    const int rbase = warpM * 16 + (lane >> 3) * 4;
    const int l7 = lane & 7;

    #pragma unroll 2
    for (int k8 = 0; k8 < KW / 8; ++k8) {
        uint4 a[4][2], b[4][2];
        #pragma unroll
        for (int rr = 0; rr < 4; ++rr) {
            int row = rbase + rr;
            const unsigned* p = sA + row * KW;
            #pragma unroll
            for (int h = 0; h < 2; ++h) {
                int k4 = 2 * k8 + h;
                a[rr][h] = *(const uint4*)(p + ((k4 ^ ((row >> 2) & 7)) << 2));
            }
        }
        #pragma unroll
        for (int jj = 0; jj < 4; ++jj) {
            int col = warpN * 32 + l7 + 8 * jj;
            const unsigned* p = sW + col * KW;
            #pragma unroll
            for (int h = 0; h < 2; ++h) {
                int k4 = 2 * k8 + h;
                b[jj][h] = *(const uint4*)(p + ((k4 ^ l7) << 2));
            }
        }
        #pragma unroll
        for (int rr = 0; rr < 4; ++rr) {
            #pragma unroll
            for (int jj = 0; jj < 4; ++jj) {
                unsigned x0 = a[rr][0].x ^ b[jj][0].x;
                unsigned x1 = a[rr][0].y ^ b[jj][0].y;
                unsigned x2 = a[rr][0].z ^ b[jj][0].z;
                unsigned x3 = a[rr][0].w ^ b[jj][0].w;
                unsigned x4 = a[rr][1].x ^ b[jj][1].x;
                unsigned x5 = a[rr][1].y ^ b[jj][1].y;
                unsigned x6 = a[rr][1].z ^ b[jj][1].z;
                unsigned x7 = a[rr][1].w ^ b[jj][1].w;
                // 4-CSA tree: popc(x0..x7) with 4 POPCs
                unsigned s1 = xor3(x0, x1, x2), c1 = maj3(x0, x1, x2);
                unsigned s2 = xor3(x3, x4, x5), c2 = maj3(x3, x4, x5);
                unsigned s3 = xor3(s1, s2, x6), c3 = maj3(s1, s2, x6);
                unsigned s4 = xor3(c1, c2, c3), c4 = maj3(c1, c2, c3);
                // all accumulates on the fma pipe (opaque-weight IMADs)
                imad_acc(acc[rr][jj], __popc(s3), w1i);
                imad_acc(acc[rr][jj], __popc(x7), w1i);
                imad_acc(acc[rr][jj], __popc(s4), w2i);
                imad_acc(acc[rr][jj], __popc(c4), w4i);
            }
        }
    }

    // ---- epilogue: BN threshold + shfl-OR repack, blocked-swizzled output ----
    const int Kbits = KW * 32;
    float t[4];
    #pragma unroll
    for (int jj = 0; jj < 4; ++jj)
        t[jj] = thr[c0 + warpN * 32 + l7 + 8 * jj];

    const int cw = (c0 >> 5) + warpN;
    #pragma unroll
    for (int rr = 0; rr < 4; ++rr) {
        unsigned v = 0;
        #pragma unroll
        for (int jj = 0; jj < 4; ++jj) {
            int C = Kbits - 2 * acc[rr][jj];
            if ((float)C < t[jj]) v |= 1u << (l7 + 8 * jj);
        }
        v |= __shfl_xor_sync(0xffffffffu, v, 1);
        v |= __shfl_xor_sync(0xffffffffu, v, 2);
        v |= __shfl_xor_sync(0xffffffffu, v, 4);
        if (l7 == 0) {
            int row = r0 + rbase + rr;
            OutN[(size_t)row * HW + SWZA(row, cw)] = v;
        }
    }
}

// ---------------- final layer: out[B][2] from blocked acts ----------------
__global__ __launch_bounds__(128)
void final_layer_kernel(const unsigned* __restrict__ AT,   // blocked [row][HW] SWZA
                        const unsigned* __restrict__ Wb,   // plain [2][HW]
                        float* __restrict__ out)
{
    __shared__ unsigned sw[2 * HW];
    if (threadIdx.x < 2 * HW) sw[threadIdx.x] = Wb[threadIdx.x];
    __syncthreads();

    int row = blockIdx.x * blockDim.x + threadIdx.x;
    const unsigned g = (row >> 2) & 7;
    const unsigned* ar = AT + (size_t)row * HW;
    int a0 = 0, a1 = 0;
    #pragma unroll
    for (int k4 = 0; k4 < HW / 4; ++k4) {
        uint4 aa = *(const uint4*)(ar + ((k4 ^ g) << 2));
        int kb = k4 * 4;
        a0 += __popc(aa.x ^ sw[kb + 0]) + __popc(aa.y ^ sw[kb + 1])
            + __popc(aa.z ^ sw[kb + 2]) + __popc(aa.w ^ sw[kb + 3]);
        a1 += __popc(aa.x ^ sw[HW + kb + 0]) + __popc(aa.y ^ sw[HW + kb + 1])
            + __popc(aa.z ^ sw[HW + kb + 2]) + __popc(aa.w ^ sw[HW + kb + 3]);
    }
    out[row * 2 + 0] = (float)(H_DIM - 2 * a0);
    out[row * 2 + 1] = (float)(H_DIM - 2 * a1);
}

// ----------------------------------------------------------------------------
extern "C" void kernel_launch(void* const* d_in, const int* in_sizes, int n_in,
                              void* d_out, int out_size)
{
    const float* x    = (const float*)d_in[0];
    const float* w1   = (const float*)d_in[1];
    const float* g1   = (const float*)d_in[2];
    const float* b1   = (const float*)d_in[3];
    const float* m1   = (const float*)d_in[4];
    const float* v1   = (const float*)d_in[5];
    const float* w2   = (const float*)d_in[6];
    const float* g2   = (const float*)d_in[7];
    const float* b2   = (const float*)d_in[8];
    const float* m2   = (const float*)d_in[9];
    const float* v2   = (const float*)d_in[10];
    const float* w3   = (const float*)d_in[11];
    const float* g3   = (const float*)d_in[12];
    const float* b3   = (const float*)d_in[13];
    const float* m3   = (const float*)d_in[14];
    const float* v3   = (const float*)d_in[15];
    const float* wout = (const float*)d_in[16];
    float* out = (float*)d_out;

    unsigned *actA, *actB, *w1b, *w2b, *w3b, *woutb;
    float* thr;
    cudaGetSymbolAddress((void**)&actA,  g_actA);
    cudaGetSymbolAddress((void**)&actB,  g_actB);
    cudaGetSymbolAddress((void**)&w1b,   g_w1);
    cudaGetSymbolAddress((void**)&w2b,   g_w2);
    cudaGetSymbolAddress((void**)&w3b,   g_w3);
    cudaGetSymbolAddress((void**)&woutb, g_woutb);
    cudaGetSymbolAddress((void**)&thr,   g_thr);

    compute_thr_all<<<(3 * H_DIM + 255) / 256, 256>>>(g1, b1, m1, v1,
                                                      g2, b2, m2, v2,
                                                      g3, b3, m3, v3, thr);

    // pack x (act = binq(2x-1) -> bit = x < 0.5) into SWZA image; weights into SWZW image
    {
        long nthr = (long)BATCH * (DW / 8) * 32;
        pack_bits_blk2<0><<<(unsigned)((nthr + 255) / 256), 256>>>((const float4*)x, actA, BATCH, DW, 0.5f);
        nthr = (long)H_DIM * (DW / 8) * 32;
        pack_bits_blk2<1><<<(unsigned)((nthr + 255) / 256), 256>>>((const float4*)w1, w1b, H_DIM, DW, 0.0f);
        nthr = (long)H_DIM * (HW / 8) * 32;
        pack_bits_blk2<1><<<(unsigned)((nthr + 255) / 256), 256>>>((const float4*)w2, w2b, H_DIM, HW, 0.0f);
        pack_bits_blk2<1><<<(unsigned)((nthr + 255) / 256), 256>>>((const float4*)w3, w3b, H_DIM, HW, 0.0f);
        pack_bits_plain<<<(O_DIM * HW * 32 + 255) / 256, 256>>>(wout, woutb, O_DIM * HW, 0.0f);
    }

    dim3 grid(BATCH / 64, H_DIM / 64);
    bgemm_csa<DW><<<grid, 256>>>(actA, w1b, thr,             actB, 1, 2, 4);
    bgemm_csa<HW><<<grid, 256>>>(actB, w2b, thr + H_DIM,     actA, 1, 2, 4);
    bgemm_csa<HW><<<grid, 256>>>(actA, w3b, thr + 2 * H_DIM, actB, 1, 2, 4);

    final_layer_kernel<<<BATCH / 128, 128>>>(actB, woutb, out);
}

// round 16
// speedup vs baseline: 1.0024x; 1.0024x over previous
#include <cuda_runtime.h>
#include <math.h>
#include <stdint.h>

// ---------------- problem dims ----------------
#define BATCH 16384
#define D_IN  1024
#define H_DIM 2048
#define O_DIM 2
#define DW (D_IN / 32)    // 32
#define HW (H_DIM / 32)   // 64

// Swizzles baked into the GLOBAL blocked layouts (match smem read patterns)
#define SWZA(row, k) ((((((k) >> 2) ^ (((row) >> 2) & 7)) << 2)) | ((k) & 3))
#define SWZW(col, k) ((((((k) >> 2) ^ ((col) & 7)) << 2)) | ((k) & 3))

// ---------------- device scratch (no allocs allowed) ----------------
__device__ __align__(16) unsigned g_actA[BATCH * HW];   // blocked [row][KW], SWZA image
__device__ __align__(16) unsigned g_actB[BATCH * HW];
__device__ __align__(16) unsigned g_w1 [H_DIM * DW];    // blocked [col][KW], SWZW image
__device__ __align__(16) unsigned g_w2 [H_DIM * HW];
__device__ __align__(16) unsigned g_w3 [H_DIM * HW];
__device__ __align__(16) unsigned g_woutb[O_DIM * HW];  // plain
__device__ float    g_thr [3 * H_DIM];

// ---------------- LOP3 helpers ----------------
__device__ __forceinline__ unsigned xor3(unsigned a, unsigned b, unsigned c) {
    unsigned r; asm("lop3.b32 %0, %1, %2, %3, 0x96;" : "=r"(r) : "r"(a), "r"(b), "r"(c)); return r;
}
__device__ __forceinline__ unsigned maj3(unsigned a, unsigned b, unsigned c) {
    unsigned r; asm("lop3.b32 %0, %1, %2, %3, 0xE8;" : "=r"(r) : "r"(a), "r"(b), "r"(c)); return r;
}
// forced IMAD accumulate (fma pipe): acc += p * w, w opaque runtime value
__device__ __forceinline__ void imad_acc(int& acc, unsigned p, int w) {
    asm("mad.lo.s32 %0, %1, %2, %0;" : "+r"(acc) : "r"(p), "r"(w));
}

// ---------------- fused thresholds (all 3 layers, one launch) ----------------
__global__ void compute_thr_all(const float* __restrict__ g1, const float* __restrict__ b1,
                                const float* __restrict__ m1, const float* __restrict__ v1,
                                const float* __restrict__ g2, const float* __restrict__ b2,
                                const float* __restrict__ m2, const float* __restrict__ v2,
                                const float* __restrict__ g3, const float* __restrict__ b3,
                                const float* __restrict__ m3, const float* __restrict__ v3,
                                float* __restrict__ thr)
{
    int i = blockIdx.x * blockDim.x + threadIdx.x;
    if (i >= 3 * H_DIM) return;
    int l = i >> 11, j = i & (H_DIM - 1);
    const float* g = (l == 0) ? g1 : (l == 1) ? g2 : g3;
    const float* b = (l == 0) ? b1 : (l == 1) ? b2 : b3;
    const float* m = (l == 0) ? m1 : (l == 1) ? m2 : m3;
    const float* v = (l == 0) ? v1 : (l == 1) ? v2 : v3;
    thr[i] = m[j] - b[j] * sqrtf(v[j] + 1e-5f) / g[j];
}

// pack src[rows][cwords*32] floats -> blocked-swizzled words. One warp = one row x 8 words,
// two independent load->ballot->shfl chains in flight (latency overlap).
// MODE 0 = activation swizzle (SWZA), MODE 1 = weight swizzle (SWZW)
template <int MODE>
__global__ void pack_bits_blk2(const float4* __restrict__ src, unsigned* __restrict__ dst,
                               int rows, int cwords, float cmp)
{
    int gid  = blockIdx.x * blockDim.x + threadIdx.x;
    int wrp  = gid >> 5;
    int lane = gid & 31;
    int wq   = cwords >> 3;              // 8-word groups per row
    if (wrp >= rows * wq) return;
    int row = wrp / wq, w0 = (wrp % wq) * 8;

    const float4* base = src + (size_t)row * (cwords * 8);
    float4 f0 = base[w0 * 8 + lane];
    float4 f1 = base[(w0 + 4) * 8 + lane];

    unsigned n0 = (f0.x < cmp ? 1u : 0u) | (f0.y < cmp ? 2u : 0u)
                | (f0.z < cmp ? 4u : 0u) | (f0.w < cmp ? 8u : 0u);
    unsigned n1 = (f1.x < cmp ? 1u : 0u) | (f1.y < cmp ? 2u : 0u)
                | (f1.z < cmp ? 4u : 0u) | (f1.w < cmp ? 8u : 0u);
    unsigned v0 = n0 << ((lane & 7) * 4);
    unsigned v1 = n1 << ((lane & 7) * 4);
    v0 |= __shfl_xor_sync(0xffffffffu, v0, 1);
    v1 |= __shfl_xor_sync(0xffffffffu, v1, 1);
    v0 |= __shfl_xor_sync(0xffffffffu, v0, 2);
    v1 |= __shfl_xor_sync(0xffffffffu, v1, 2);
    v0 |= __shfl_xor_sync(0xffffffffu, v0, 4);
    v1 |= __shfl_xor_sync(0xffffffffu, v1, 4);
    if ((lane & 7) == 0) {
        int wA = w0 + (lane >> 3);
        int wB = wA + 4;
        int sA = (MODE == 0) ? SWZA(row, wA) : SWZW(row, wA);
        int sB = (MODE == 0) ? SWZA(row, wB) : SWZW(row, wB);
        dst[(size_t)row * cwords + sA] = v0;
        dst[(size_t)row * cwords + sB] = v1;
    }
}

__global__ void pack_bits_plain(const float* __restrict__ src, unsigned* __restrict__ dst,
                                int nwords, float cmp)
{
    int gid = blockIdx.x * blockDim.x + threadIdx.x;
    int w = gid >> 5;
    if (w >= nwords) return;
    int lane = gid & 31;
    float v = src[(size_t)w * 32 + lane];
    unsigned msk = __ballot_sync(0xffffffffu, v < cmp);
    if (lane == 0) dst[w] = msk;
}

// ---------------- CSA-popc binary GEMM (R7/R9 structure; IMAD accumulate) ----------------
// CTA tile 64 rows x 64 cols, 256 threads = 8 warps (4 row-groups x 2 col-groups).
// Warp: 16 rows x 32 cols. Lane: 4 rows x 4 cols; 8-word K window, 4-CSA tree.
template <int KW>
__global__ __launch_bounds__(256, 2)
void bgemm_csa(const unsigned* __restrict__ Apk,   // blocked [row][KW] SWZA image
               const unsigned* __restrict__ Wpk,   // blocked [col][KW] SWZW image
               const float*    __restrict__ thr,
               unsigned*       __restrict__ OutN,  // blocked [row][HW] SWZA image
               int w1i, int w2i, int w4i)          // opaque 1, 2, 4
{
    __shared__ unsigned sA[64 * KW];
    __shared__ unsigned sW[64 * KW];

    const int tid  = threadIdx.x;
    const int lane = tid & 31;
    const int wid  = tid >> 5;
    const int warpM = wid & 3;
    const int warpN = wid >> 2;
    const int r0 = blockIdx.x * 64;
    const int c0 = blockIdx.y * 64;

    // linear vectorized fills: global image == smem image (swizzle pre-baked)
    {
        const uint4* asrc = (const uint4*)(Apk + (size_t)r0 * KW);
        uint4* ad = (uint4*)sA;
        #pragma unroll
        for (int i = tid; i < 16 * KW; i += 256) ad[i] = asrc[i];
        const uint4* wsrc = (const uint4*)(Wpk + (size_t)c0 * KW);
        uint4* wd = (uint4*)sW;
        #pragma unroll
        for (int i = tid; i < 16 * KW; i += 256) wd[i] = wsrc[i];
    }
    __syncthreads();

    int acc[4][4];
    #pragma unroll
    for (int r = 0; r < 4; ++r)
        #pragma unroll
        for (int j = 0; j < 4; ++j) acc[r][j] = 0;

    const int rbase = warpM * 16 + (lane >> 3) * 4;
    const int l7 = lane & 7;

    #pragma unroll 2
    for (int k8 = 0; k8 < KW / 8; ++k8) {
        uint4 a[4][2], b[4][2];
        #pragma unroll
        for (int rr = 0; rr < 4; ++rr) {
            int row = rbase + rr;
            const unsigned* p = sA + row * KW;
            #pragma unroll
            for (int h = 0; h < 2; ++h) {
                int k4 = 2 * k8 + h;
                a[rr][h] = *(const uint4*)(p + ((k4 ^ ((row >> 2) & 7)) << 2));
            }
        }
        #pragma unroll
        for (int jj = 0; jj < 4; ++jj) {
            int col = warpN * 32 + l7 + 8 * jj;
            const unsigned* p = sW + col * KW;
            #pragma unroll
            for (int h = 0; h < 2; ++h) {
                int k4 = 2 * k8 + h;
                b[jj][h] = *(const uint4*)(p + ((k4 ^ l7) << 2));
            }
        }
        #pragma unroll
        for (int rr = 0; rr < 4; ++rr) {
            #pragma unroll
            for (int jj = 0; jj < 4; ++jj) {
                unsigned x0 = a[rr][0].x ^ b[jj][0].x;
                unsigned x1 = a[rr][0].y ^ b[jj][0].y;
                unsigned x2 = a[rr][0].z ^ b[jj][0].z;
                unsigned x3 = a[rr][0].w ^ b[jj][0].w;
                unsigned x4 = a[rr][1].x ^ b[jj][1].x;
                unsigned x5 = a[rr][1].y ^ b[jj][1].y;
                unsigned x6 = a[rr][1].z ^ b[jj][1].z;
                unsigned x7 = a[rr][1].w ^ b[jj][1].w;
                // 4-CSA tree: popc(x0..x7) with 4 POPCs
                unsigned s1 = xor3(x0, x1, x2), c1 = maj3(x0, x1, x2);
                unsigned s2 = xor3(x3, x4, x5), c2 = maj3(x3, x4, x5);
                unsigned s3 = xor3(s1, s2, x6), c3 = maj3(s1, s2, x6);
                unsigned s4 = xor3(c1, c2, c3), c4 = maj3(c1, c2, c3);
                // all accumulates on the fma pipe (opaque-weight IMADs)
                imad_acc(acc[rr][jj], __popc(s3), w1i);
                imad_acc(acc[rr][jj], __popc(x7), w1i);
                imad_acc(acc[rr][jj], __popc(s4), w2i);
                imad_acc(acc[rr][jj], __popc(c4), w4i);
            }
        }
    }

    // ---- epilogue: BN threshold + shfl-OR repack, blocked-swizzled output ----
    const int Kbits = KW * 32;
    float t[4];
    #pragma unroll
    for (int jj = 0; jj < 4; ++jj)
        t[jj] = thr[c0 + warpN * 32 + l7 + 8 * jj];

    const int cw = (c0 >> 5) + warpN;
    #pragma unroll
    for (int rr = 0; rr < 4; ++rr) {
        unsigned v = 0;
        #pragma unroll
        for (int jj = 0; jj < 4; ++jj) {
            int C = Kbits - 2 * acc[rr][jj];
            if ((float)C < t[jj]) v |= 1u << (l7 + 8 * jj);
        }
        v |= __shfl_xor_sync(0xffffffffu, v, 1);
        v |= __shfl_xor_sync(0xffffffffu, v, 2);
        v |= __shfl_xor_sync(0xffffffffu, v, 4);
        if (l7 == 0) {
            int row = r0 + rbase + rr;
            OutN[(size_t)row * HW + SWZA(row, cw)] = v;
        }
    }
}

// ---------------- final layer: out[B][2] from blocked acts ----------------
__global__ __launch_bounds__(128)
void final_layer_kernel(const unsigned* __restrict__ AT,   // blocked [row][HW] SWZA
                        const unsigned* __restrict__ Wb,   // plain [2][HW]
                        float* __restrict__ out)
{
    __shared__ unsigned sw[2 * HW];
    if (threadIdx.x < 2 * HW) sw[threadIdx.x] = Wb[threadIdx.x];
    __syncthreads();

    int row = blockIdx.x * blockDim.x + threadIdx.x;
    const unsigned g = (row >> 2) & 7;
    const unsigned* ar = AT + (size_t)row * HW;
    int a0 = 0, a1 = 0;
    #pragma unroll
    for (int k4 = 0; k4 < HW / 4; ++k4) {
        uint4 aa = *(const uint4*)(ar + ((k4 ^ g) << 2));
        int kb = k4 * 4;
        a0 += __popc(aa.x ^ sw[kb + 0]) + __popc(aa.y ^ sw[kb + 1])
            + __popc(aa.z ^ sw[kb + 2]) + __popc(aa.w ^ sw[kb + 3]);
        a1 += __popc(aa.x ^ sw[HW + kb + 0]) + __popc(aa.y ^ sw[HW + kb + 1])
            + __popc(aa.z ^ sw[HW + kb + 2]) + __popc(aa.w ^ sw[HW + kb + 3]);
    }
    out[row * 2 + 0] = (float)(H_DIM - 2 * a0);
    out[row * 2 + 1] = (float)(H_DIM - 2 * a1);
}

// ----------------------------------------------------------------------------
extern "C" void kernel_launch(void* const* d_in, const int* in_sizes, int n_in,
                              void* d_out, int out_size)
{
    const float* x    = (const float*)d_in[0];
    const float* w1   = (const float*)d_in[1];
    const float* g1   = (const float*)d_in[2];
    const float* b1   = (const float*)d_in[3];
    const float* m1   = (const float*)d_in[4];
    const float* v1   = (const float*)d_in[5];
    const float* w2   = (const float*)d_in[6];
    const float* g2   = (const float*)d_in[7];
    const float* b2   = (const float*)d_in[8];
    const float* m2   = (const float*)d_in[9];
    const float* v2   = (const float*)d_in[10];
    const float* w3   = (const float*)d_in[11];
    const float* g3   = (const float*)d_in[12];
    const float* b3   = (const float*)d_in[13];
    const float* m3   = (const float*)d_in[14];
    const float* v3   = (const float*)d_in[15];
    const float* wout = (const float*)d_in[16];
    float* out = (float*)d_out;

    unsigned *actA, *actB, *w1b, *w2b, *w3b, *woutb;
    float* thr;
    cudaGetSymbolAddress((void**)&actA,  g_actA);
    cudaGetSymbolAddress((void**)&actB,  g_actB);
    cudaGetSymbolAddress((void**)&w1b,   g_w1);
    cudaGetSymbolAddress((void**)&w2b,   g_w2);
    cudaGetSymbolAddress((void**)&w3b,   g_w3);
    cudaGetSymbolAddress((void**)&woutb, g_woutb);
    cudaGetSymbolAddress((void**)&thr,   g_thr);

    compute_thr_all<<<(3 * H_DIM + 255) / 256, 256>>>(g1, b1, m1, v1,
                                                      g2, b2, m2, v2,
                                                      g3, b3, m3, v3, thr);

    // pack x (act = binq(2x-1) -> bit = x < 0.5) into SWZA image; weights into SWZW image
    {
        long nthr = (long)BATCH * (DW / 8) * 32;
        pack_bits_blk2<0><<<(unsigned)((nthr + 255) / 256), 256>>>((const float4*)x, actA, BATCH, DW, 0.5f);
        nthr = (long)H_DIM * (DW / 8) * 32;
        pack_bits_blk2<1><<<(unsigned)((nthr + 255) / 256), 256>>>((const float4*)w1, w1b, H_DIM, DW, 0.0f);
        nthr = (long)H_DIM * (HW / 8) * 32;
        pack_bits_blk2<1><<<(unsigned)((nthr + 255) / 256), 256>>>((const float4*)w2, w2b, H_DIM, HW, 0.0f);
        pack_bits_blk2<1><<<(unsigned)((nthr + 255) / 256), 256>>>((const float4*)w3, w3b, H_DIM, HW, 0.0f);
        pack_bits_plain<<<(O_DIM * HW * 32 + 255) / 256, 256>>>(wout, woutb, O_DIM * HW, 0.0f);
    }

    dim3 grid(BATCH / 64, H_DIM / 64);
    bgemm_csa<DW><<<grid, 256>>>(actA, w1b, thr,             actB, 1, 2, 4);
    bgemm_csa<HW><<<grid, 256>>>(actB, w2b, thr + H_DIM,     actA, 1, 2, 4);
    bgemm_csa<HW><<<grid, 256>>>(actA, w3b, thr + 2 * H_DIM, actB, 1, 2, 4);

    final_layer_kernel<<<BATCH / 128, 128>>>(actB, woutb, out);
}